// round 3
// baseline (speedup 1.0000x reference)
#include <cuda_runtime.h>

// R3 = R2 resubmitted: previous round failed on container infra, not kernel.

#define L_NODES 30000
#define JDIM 64
#define NFEAT 16

// Scratch (allocation-free): per-node tables + transposed Wb.
__device__ float g_hXWt[L_NODES * JDIM];
__device__ float g_hXWb[L_NODES * JDIM];
__device__ float g_WbT[JDIM * JDIM];   // g_WbT[j*64+k] = g1w[(64+k)*64 + j]

// ---------------------------------------------------------------------------
// Tiny transpose: Wb (bottom half of g1_w) -> column-major table so main
// kernel threads can load their column with LDG.128.
// ---------------------------------------------------------------------------
__global__ void transpose_wb_kernel(const float* __restrict__ g1w)
{
    int j = blockIdx.x;      // output column
    int k = threadIdx.x;     // k index
    g_WbT[j * 64 + k] = g1w[(64 + k) * 64 + j];
}

// ---------------------------------------------------------------------------
// Prep: hx = relu(X@h1_w+h1_b);  hXWt = hx@Wt;  hXWb = hx@Wb.
// Few big persistent blocks so the 36KB weight stage is amortized over many
// nodes (R1 version paid 36KB L2 traffic per 4 nodes -> ~64us).
// Block = 1024 threads = 16 node-lanes x 64; grid-stride over 1875 groups.
// ---------------------------------------------------------------------------
__global__ __launch_bounds__(1024) void prep_kernel(
    const float* __restrict__ X,
    const float* __restrict__ h1w,
    const float* __restrict__ h1b,
    const float* __restrict__ g1w)
{
    __shared__ __align__(16) float s_gw[128 * 64];  // Wt rows 0..63, Wb rows 64..127
    __shared__ __align__(16) float s_h1w[16 * 64];
    __shared__ float s_h1b[64];
    __shared__ __align__(16) float s_hx[16][64];

    int tid = threadIdx.x;
    for (int i = tid; i < 128 * 64; i += 1024) s_gw[i]  = g1w[i];
    for (int i = tid; i < 16 * 64;  i += 1024) s_h1w[i] = h1w[i];
    if (tid < 64) s_h1b[tid] = h1b[tid];
    __syncthreads();

    int g = tid >> 6;
    int j = tid & 63;

    const int NGROUPS = L_NODES / 16;   // 1875 exactly
    for (int grp = blockIdx.x; grp < NGROUPS; grp += gridDim.x) {
        int l = grp * 16 + g;

        // hx_j = relu(sum_k X[l][k] * h1w[k][j] + b[j])
        const float4* xr = (const float4*)(X + l * NFEAT);
        float4 x0 = xr[0], x1 = xr[1], x2 = xr[2], x3 = xr[3];
        float acc = s_h1b[j];
        acc = fmaf(x0.x, s_h1w[ 0 * 64 + j], acc);
        acc = fmaf(x0.y, s_h1w[ 1 * 64 + j], acc);
        acc = fmaf(x0.z, s_h1w[ 2 * 64 + j], acc);
        acc = fmaf(x0.w, s_h1w[ 3 * 64 + j], acc);
        acc = fmaf(x1.x, s_h1w[ 4 * 64 + j], acc);
        acc = fmaf(x1.y, s_h1w[ 5 * 64 + j], acc);
        acc = fmaf(x1.z, s_h1w[ 6 * 64 + j], acc);
        acc = fmaf(x1.w, s_h1w[ 7 * 64 + j], acc);
        acc = fmaf(x2.x, s_h1w[ 8 * 64 + j], acc);
        acc = fmaf(x2.y, s_h1w[ 9 * 64 + j], acc);
        acc = fmaf(x2.z, s_h1w[10 * 64 + j], acc);
        acc = fmaf(x2.w, s_h1w[11 * 64 + j], acc);
        acc = fmaf(x3.x, s_h1w[12 * 64 + j], acc);
        acc = fmaf(x3.y, s_h1w[13 * 64 + j], acc);
        acc = fmaf(x3.z, s_h1w[14 * 64 + j], acc);
        acc = fmaf(x3.w, s_h1w[15 * 64 + j], acc);
        s_hx[g][j] = fmaxf(acc, 0.0f);
        __syncthreads();

        // at = hx @ Wt[:,j], ab = hx @ Wb[:,j]; hx broadcast via LDS.128
        float at = 0.0f, ab = 0.0f;
        const float4* vp = (const float4*)s_hx[g];
#pragma unroll
        for (int k4 = 0; k4 < 16; k4++) {
            float4 v = vp[k4];
            int r = 4 * k4;
            at = fmaf(v.x, s_gw[(r + 0) * 64 + j], at);
            at = fmaf(v.y, s_gw[(r + 1) * 64 + j], at);
            at = fmaf(v.z, s_gw[(r + 2) * 64 + j], at);
            at = fmaf(v.w, s_gw[(r + 3) * 64 + j], at);
            ab = fmaf(v.x, s_gw[(64 + r + 0) * 64 + j], ab);
            ab = fmaf(v.y, s_gw[(64 + r + 1) * 64 + j], ab);
            ab = fmaf(v.z, s_gw[(64 + r + 2) * 64 + j], ab);
            ab = fmaf(v.w, s_gw[(64 + r + 3) * 64 + j], ab);
        }
        g_hXWt[l * 64 + j] = at;
        g_hXWb[l * 64 + j] = ab;
        __syncthreads();   // s_hx reused next iteration
    }
}

// ---------------------------------------------------------------------------
// Main: per-node subset DP (logic identical to R1 passing version).
// Matvecs read broadcast vectors with LDS.128 (4x fewer L1 wavefronts)
// and interleave accumulator chains k-outer for ILP.
// ---------------------------------------------------------------------------
__global__ __launch_bounds__(256) void ggcn_main_kernel(
    const int*   __restrict__ nbr,
    const float* __restrict__ g1b,
    const float* __restrict__ fw,
    const float* __restrict__ fb,
    float*       __restrict__ out)
{
    __shared__ __align__(16) float s_buf[4][6][64];
    __shared__ __align__(16) float s_e2[4][64];

    int tid = threadIdx.x;
    int g = tid >> 6;
    int j = tid & 63;
    int l = blockIdx.x * 4 + g;

    // Wb column j -> registers, via transposed table (LDG.128 x16)
    float w[64];
    {
        const float4* wt = (const float4*)(g_WbT + j * 64);
#pragma unroll
        for (int k4 = 0; k4 < 16; k4++) {
            float4 t = wt[k4];
            w[4 * k4 + 0] = t.x;
            w[4 * k4 + 1] = t.y;
            w[4 * k4 + 2] = t.z;
            w[4 * k4 + 3] = t.w;
        }
    }
    float b = g1b[j];

    int4 nb = ((const int4*)nbr)[l];
    int ni[4] = {nb.x, nb.y, nb.z, nb.w};
    float A[4], Bv[4];
#pragma unroll
    for (int i = 0; i < 4; i++) {
        A[i]  = g_hXWt[ni[i] * 64 + j];
        Bv[i] = g_hXWb[ni[i] * 64 + j];
    }
    float hxwt = g_hXWt[l * 64 + j];

    // ---- pairs ----
    const int PA[6] = {0, 0, 0, 1, 1, 2};
    const int PB[6] = {1, 2, 3, 2, 3, 3};
#pragma unroll
    for (int p = 0; p < 6; p++) {
        int i0 = PA[p], i1 = PB[p];
        s_buf[g][p][j] = 0.5f * (fmaxf(A[i0] + Bv[i1] + b, 0.0f) +
                                 fmaxf(A[i1] + Bv[i0] + b, 0.0f));
    }
    __syncthreads();

    float PWb[6] = {0.f, 0.f, 0.f, 0.f, 0.f, 0.f};
#pragma unroll
    for (int k4 = 0; k4 < 16; k4++) {
#pragma unroll
        for (int p = 0; p < 6; p++) {
            float4 v = ((const float4*)s_buf[g][p])[k4];
            PWb[p] = fmaf(v.x, w[4 * k4 + 0], PWb[p]);
            PWb[p] = fmaf(v.y, w[4 * k4 + 1], PWb[p]);
            PWb[p] = fmaf(v.z, w[4 * k4 + 2], PWb[p]);
            PWb[p] = fmaf(v.w, w[4 * k4 + 3], PWb[p]);
        }
    }
    __syncthreads();   // s_buf about to be overwritten

    // ---- triples (indexed by missing element m) ----
    const int PIDX[4][4] = {{-1, 0, 1, 2},
                            { 0,-1, 3, 4},
                            { 1, 3,-1, 5},
                            { 2, 4, 5,-1}};
#pragma unroll
    for (int m = 0; m < 4; m++) {
        float acc = 0.0f;
#pragma unroll
        for (int i = 0; i < 4; i++) {
            if (i == m) continue;
            int a = -1, c = -1;
#pragma unroll
            for (int t = 0; t < 4; t++) {
                if (t != m && t != i) { if (a < 0) a = t; else c = t; }
            }
            acc += fmaxf(A[i] + PWb[PIDX[a][c]] + b, 0.0f);
        }
        s_buf[g][m][j] = acc * (1.0f / 3.0f);
    }
    __syncthreads();

    float TWb[4] = {0.f, 0.f, 0.f, 0.f};
#pragma unroll
    for (int k4 = 0; k4 < 16; k4++) {
#pragma unroll
        for (int m = 0; m < 4; m++) {
            float4 v = ((const float4*)s_buf[g][m])[k4];
            TWb[m] = fmaf(v.x, w[4 * k4 + 0], TWb[m]);
            TWb[m] = fmaf(v.y, w[4 * k4 + 1], TWb[m]);
            TWb[m] = fmaf(v.z, w[4 * k4 + 2], TWb[m]);
            TWb[m] = fmaf(v.w, w[4 * k4 + 3], TWb[m]);
        }
    }
    __syncthreads();   // s_buf reused for E

    // ---- quad + readout head ----
    float q = 0.0f;
#pragma unroll
    for (int i = 0; i < 4; i++) q += fmaxf(A[i] + TWb[i] + b, 0.0f);
    s_buf[g][0][j] = fmaxf(q * 0.25f, 0.0f);   // E
    __syncthreads();

    float a0 = 0.f, a1 = 0.f, a2 = 0.f, a3 = 0.f;
#pragma unroll
    for (int k4 = 0; k4 < 16; k4++) {
        float4 v = ((const float4*)s_buf[g][0])[k4];
        a0 = fmaf(v.x, w[4 * k4 + 0], a0);
        a1 = fmaf(v.y, w[4 * k4 + 1], a1);
        a2 = fmaf(v.z, w[4 * k4 + 2], a2);
        a3 = fmaf(v.w, w[4 * k4 + 3], a3);
    }
    float E2 = fmaxf(hxwt + ((a0 + a1) + (a2 + a3)) + b, 0.0f);
    s_e2[g][j] = E2;
    __syncthreads();

    if (j < 2) {
        float y = fb[j];
        const float4* ep = (const float4*)s_e2[g];
#pragma unroll
        for (int k4 = 0; k4 < 16; k4++) {
            float4 v = ep[k4];
            y = fmaf(v.x, fw[(4 * k4 + 0) * 2 + j], y);
            y = fmaf(v.y, fw[(4 * k4 + 1) * 2 + j], y);
            y = fmaf(v.z, fw[(4 * k4 + 2) * 2 + j], y);
            y = fmaf(v.w, fw[(4 * k4 + 3) * 2 + j], y);
        }
        out[l * 2 + j] = y;
    }
}

// ---------------------------------------------------------------------------
// kernel_launch: graph-capturable, allocation-free.
// Inputs: X, neighbors, h1_w, h1_b, g1_w, g1_b, final_w, final_b
// ---------------------------------------------------------------------------
extern "C" void kernel_launch(void* const* d_in, const int* in_sizes, int n_in,
                              void* d_out, int out_size)
{
    const float* X    = (const float*)d_in[0];
    const int*   nbr  = (const int*)  d_in[1];
    const float* h1w  = (const float*)d_in[2];
    const float* h1b  = (const float*)d_in[3];
    const float* g1w  = (const float*)d_in[4];
    const float* g1b  = (const float*)d_in[5];
    const float* fw   = (const float*)d_in[6];
    const float* fb   = (const float*)d_in[7];
    float* out = (float*)d_out;

    (void)in_sizes; (void)n_in; (void)out_size;

    transpose_wb_kernel<<<64, 64>>>(g1w);
    prep_kernel<<<296, 1024>>>(X, h1w, h1b, g1w);
    ggcn_main_kernel<<<(L_NODES + 3) / 4, 256>>>(nbr, g1b, fw, fb, out);
}

// round 4
// speedup vs baseline: 1.7046x; 1.7046x over previous
#include <cuda_runtime.h>

#define L_NODES 30000
#define JDIM 64
#define NFEAT 16

// Scratch (allocation-free): per-node tables.
__device__ float g_hXWt[L_NODES * JDIM];
__device__ float g_hXWb[L_NODES * JDIM];

// ---------------------------------------------------------------------------
// Prep: hx = relu(X@h1_w+h1_b);  hXWt = hx@Wt;  hXWb = hx@Wb.
// Thread j owns column j of h1w/Wt/Wb IN REGISTERS (144 regs) so the shared
// crossbar only carries float4 *broadcasts* of hx (cheap), not weight bytes.
// Block = 256 threads = 4 node-lanes x 64; persistent grid-stride.
// ---------------------------------------------------------------------------
__global__ __launch_bounds__(256, 1) void prep_kernel(
    const float* __restrict__ X,
    const float* __restrict__ h1w,
    const float* __restrict__ h1b,
    const float* __restrict__ g1w)
{
    __shared__ __align__(16) float s_hx[4][64];

    int tid = threadIdx.x;
    int g = tid >> 6;
    int j = tid & 63;

    // Column j of each weight matrix -> registers (coalesced across lanes).
    float wh[16], wt[64], wb[64];
#pragma unroll
    for (int k = 0; k < 16; k++) wh[k] = h1w[k * 64 + j];
#pragma unroll
    for (int k = 0; k < 64; k++) {
        wt[k] = g1w[k * 64 + j];
        wb[k] = g1w[(64 + k) * 64 + j];
    }
    float bj = h1b[j];

    const int NGROUPS = L_NODES / 4;   // 7500
    for (int grp = blockIdx.x; grp < NGROUPS; grp += gridDim.x) {
        int l = grp * 4 + g;

        // All 64 threads of a lane read the same X row -> LDG broadcast.
        const float4* xr = (const float4*)(X + l * NFEAT);
        float4 x0 = xr[0], x1 = xr[1], x2 = xr[2], x3 = xr[3];
        float acc = bj;
        acc = fmaf(x0.x, wh[ 0], acc); acc = fmaf(x0.y, wh[ 1], acc);
        acc = fmaf(x0.z, wh[ 2], acc); acc = fmaf(x0.w, wh[ 3], acc);
        acc = fmaf(x1.x, wh[ 4], acc); acc = fmaf(x1.y, wh[ 5], acc);
        acc = fmaf(x1.z, wh[ 6], acc); acc = fmaf(x1.w, wh[ 7], acc);
        acc = fmaf(x2.x, wh[ 8], acc); acc = fmaf(x2.y, wh[ 9], acc);
        acc = fmaf(x2.z, wh[10], acc); acc = fmaf(x2.w, wh[11], acc);
        acc = fmaf(x3.x, wh[12], acc); acc = fmaf(x3.y, wh[13], acc);
        acc = fmaf(x3.z, wh[14], acc); acc = fmaf(x3.w, wh[15], acc);
        s_hx[g][j] = fmaxf(acc, 0.0f);
        __syncthreads();

        // at = hx @ Wt[:,j], ab = hx @ Wb[:,j]; hx via float4 broadcast LDS.
        float at = 0.0f, ab = 0.0f;
        const float4* vp = (const float4*)s_hx[g];
#pragma unroll
        for (int k4 = 0; k4 < 16; k4++) {
            float4 v = vp[k4];
            int r = 4 * k4;
            at = fmaf(v.x, wt[r + 0], at);  ab = fmaf(v.x, wb[r + 0], ab);
            at = fmaf(v.y, wt[r + 1], at);  ab = fmaf(v.y, wb[r + 1], ab);
            at = fmaf(v.z, wt[r + 2], at);  ab = fmaf(v.z, wb[r + 2], ab);
            at = fmaf(v.w, wt[r + 3], at);  ab = fmaf(v.w, wb[r + 3], ab);
        }
        g_hXWt[l * 64 + j] = at;
        g_hXWb[l * 64 + j] = ab;
        __syncthreads();   // s_hx reused next iteration
    }
}

// ---------------------------------------------------------------------------
// Main: per-node subset DP (logic identical to R1 passing version).
// All matvec reads are float4 BROADCASTS (4x fewer L1 wavefronts than R1's
// scalar broadcasts). 2-way accumulator interleave bounds register pressure;
// __launch_bounds__(256,2) restores the 128-reg / 2-blocks-per-SM operating
// point that R1 ran at.
// ---------------------------------------------------------------------------
__global__ __launch_bounds__(256, 2) void ggcn_main_kernel(
    const int*   __restrict__ nbr,
    const float* __restrict__ g1w,
    const float* __restrict__ g1b,
    const float* __restrict__ fw,
    const float* __restrict__ fb,
    float*       __restrict__ out)
{
    __shared__ __align__(16) float s_buf[4][6][64];
    __shared__ __align__(16) float s_e2[4][64];

    int tid = threadIdx.x;
    int g = tid >> 6;
    int j = tid & 63;
    int l = blockIdx.x * 4 + g;

    // Wb column j -> registers (coalesced strided LDG, L1/L2-resident)
    float w[64];
#pragma unroll
    for (int k = 0; k < 64; k++) w[k] = __ldg(&g1w[(64 + k) * 64 + j]);
    float b = g1b[j];

    int4 nb = ((const int4*)nbr)[l];
    int ni[4] = {nb.x, nb.y, nb.z, nb.w};
    float A[4], Bv[4];
#pragma unroll
    for (int i = 0; i < 4; i++) {
        A[i]  = g_hXWt[ni[i] * 64 + j];
        Bv[i] = g_hXWb[ni[i] * 64 + j];
    }
    float hxwt = g_hXWt[l * 64 + j];

    // ---- pairs ----
    const int PA[6] = {0, 0, 0, 1, 1, 2};
    const int PB[6] = {1, 2, 3, 2, 3, 3};
#pragma unroll
    for (int p = 0; p < 6; p++) {
        int i0 = PA[p], i1 = PB[p];
        s_buf[g][p][j] = 0.5f * (fmaxf(A[i0] + Bv[i1] + b, 0.0f) +
                                 fmaxf(A[i1] + Bv[i0] + b, 0.0f));
    }
    __syncthreads();

    float PWb[6];
#pragma unroll
    for (int p = 0; p < 6; p += 2) {
        float a0 = 0.f, a1 = 0.f;
        const float4* v0 = (const float4*)s_buf[g][p];
        const float4* v1 = (const float4*)s_buf[g][p + 1];
#pragma unroll
        for (int k4 = 0; k4 < 16; k4++) {
            float4 u = v0[k4], t = v1[k4];
            int r = 4 * k4;
            a0 = fmaf(u.x, w[r + 0], a0);  a1 = fmaf(t.x, w[r + 0], a1);
            a0 = fmaf(u.y, w[r + 1], a0);  a1 = fmaf(t.y, w[r + 1], a1);
            a0 = fmaf(u.z, w[r + 2], a0);  a1 = fmaf(t.z, w[r + 2], a1);
            a0 = fmaf(u.w, w[r + 3], a0);  a1 = fmaf(t.w, w[r + 3], a1);
        }
        PWb[p] = a0;
        PWb[p + 1] = a1;
    }
    __syncthreads();   // s_buf about to be overwritten

    // ---- triples (indexed by missing element m) ----
    const int PIDX[4][4] = {{-1, 0, 1, 2},
                            { 0,-1, 3, 4},
                            { 1, 3,-1, 5},
                            { 2, 4, 5,-1}};
#pragma unroll
    for (int m = 0; m < 4; m++) {
        float acc = 0.0f;
#pragma unroll
        for (int i = 0; i < 4; i++) {
            if (i == m) continue;
            int a = -1, c = -1;
#pragma unroll
            for (int t = 0; t < 4; t++) {
                if (t != m && t != i) { if (a < 0) a = t; else c = t; }
            }
            acc += fmaxf(A[i] + PWb[PIDX[a][c]] + b, 0.0f);
        }
        s_buf[g][m][j] = acc * (1.0f / 3.0f);
    }
    __syncthreads();

    float TWb[4];
#pragma unroll
    for (int m = 0; m < 4; m += 2) {
        float a0 = 0.f, a1 = 0.f;
        const float4* v0 = (const float4*)s_buf[g][m];
        const float4* v1 = (const float4*)s_buf[g][m + 1];
#pragma unroll
        for (int k4 = 0; k4 < 16; k4++) {
            float4 u = v0[k4], t = v1[k4];
            int r = 4 * k4;
            a0 = fmaf(u.x, w[r + 0], a0);  a1 = fmaf(t.x, w[r + 0], a1);
            a0 = fmaf(u.y, w[r + 1], a0);  a1 = fmaf(t.y, w[r + 1], a1);
            a0 = fmaf(u.z, w[r + 2], a0);  a1 = fmaf(t.z, w[r + 2], a1);
            a0 = fmaf(u.w, w[r + 3], a0);  a1 = fmaf(t.w, w[r + 3], a1);
        }
        TWb[m] = a0;
        TWb[m + 1] = a1;
    }
    __syncthreads();   // s_buf reused for E

    // ---- quad + readout head ----
    float q = 0.0f;
#pragma unroll
    for (int i = 0; i < 4; i++) q += fmaxf(A[i] + TWb[i] + b, 0.0f);
    s_buf[g][0][j] = fmaxf(q * 0.25f, 0.0f);   // E
    __syncthreads();

    float a0 = 0.f, a1 = 0.f;
#pragma unroll
    for (int k4 = 0; k4 < 16; k4++) {
        float4 v = ((const float4*)s_buf[g][0])[k4];
        int r = 4 * k4;
        a0 = fmaf(v.x, w[r + 0], a0);  a1 = fmaf(v.y, w[r + 1], a1);
        a0 = fmaf(v.z, w[r + 2], a0);  a1 = fmaf(v.w, w[r + 3], a1);
    }
    float E2 = fmaxf(hxwt + (a0 + a1) + b, 0.0f);
    s_e2[g][j] = E2;
    __syncthreads();

    if (j < 2) {
        float y = fb[j];
        const float4* ep = (const float4*)s_e2[g];
#pragma unroll
        for (int k4 = 0; k4 < 16; k4++) {
            float4 v = ep[k4];
            y = fmaf(v.x, fw[(4 * k4 + 0) * 2 + j], y);
            y = fmaf(v.y, fw[(4 * k4 + 1) * 2 + j], y);
            y = fmaf(v.z, fw[(4 * k4 + 2) * 2 + j], y);
            y = fmaf(v.w, fw[(4 * k4 + 3) * 2 + j], y);
        }
        out[l * 2 + j] = y;
    }
}

// ---------------------------------------------------------------------------
// kernel_launch: graph-capturable, allocation-free.
// Inputs: X, neighbors, h1_w, h1_b, g1_w, g1_b, final_w, final_b
// ---------------------------------------------------------------------------
extern "C" void kernel_launch(void* const* d_in, const int* in_sizes, int n_in,
                              void* d_out, int out_size)
{
    const float* X    = (const float*)d_in[0];
    const int*   nbr  = (const int*)  d_in[1];
    const float* h1w  = (const float*)d_in[2];
    const float* h1b  = (const float*)d_in[3];
    const float* g1w  = (const float*)d_in[4];
    const float* g1b  = (const float*)d_in[5];
    const float* fw   = (const float*)d_in[6];
    const float* fb   = (const float*)d_in[7];
    float* out = (float*)d_out;

    (void)in_sizes; (void)n_in; (void)out_size;

    prep_kernel<<<592, 256>>>(X, h1w, h1b, g1w);
    ggcn_main_kernel<<<(L_NODES + 3) / 4, 256>>>(nbr, g1w, g1b, fw, fb, out);
}

// round 6
// speedup vs baseline: 2.1289x; 1.2489x over previous
#include <cuda_runtime.h>

// R6 = R5 resubmitted unchanged: R5 bench died on container infra (twice),
// kernel never executed. No evidence to update on.

#define L_NODES 30000
#define JDIM 64
#define NFEAT 16

// Scratch (allocation-free): per-node tables.
__device__ float g_hXWt[L_NODES * JDIM];
__device__ float g_hXWb[L_NODES * JDIM];

// ---- packed f32x2 helpers (Blackwell sm_100+) --------------------------------
__device__ __forceinline__ unsigned long long pack2(float lo, float hi) {
    unsigned long long r;
    asm("mov.b64 %0, {%1, %2};" : "=l"(r) : "f"(lo), "f"(hi));
    return r;
}
__device__ __forceinline__ void unpack2(unsigned long long v, float& lo, float& hi) {
    asm("mov.b64 {%0, %1}, %2;" : "=f"(lo), "=f"(hi) : "l"(v));
}
// d = a*b + d (elementwise on (lo,hi))
__device__ __forceinline__ void ffma2(unsigned long long& d,
                                      unsigned long long a, unsigned long long b) {
    asm("fma.rn.f32x2 %0, %1, %2, %0;" : "+l"(d) : "l"(a), "l"(b));
}
__device__ __forceinline__ float hsum2(unsigned long long v) {
    float lo, hi; unpack2(v, lo, hi); return lo + hi;
}

// ---------------------------------------------------------------------------
// Prep (R4-measured ~23us): hx = relu(X@h1_w+h1_b); hXWt = hx@Wt; hXWb = hx@Wb.
// Weights in registers, persistent blocks.
// ---------------------------------------------------------------------------
__global__ __launch_bounds__(256, 1) void prep_kernel(
    const float* __restrict__ X,
    const float* __restrict__ h1w,
    const float* __restrict__ h1b,
    const float* __restrict__ g1w)
{
    __shared__ __align__(16) float s_hx[4][64];

    int tid = threadIdx.x;
    int g = tid >> 6;
    int j = tid & 63;

    float wh[16], wt[64], wb[64];
#pragma unroll
    for (int k = 0; k < 16; k++) wh[k] = h1w[k * 64 + j];
#pragma unroll
    for (int k = 0; k < 64; k++) {
        wt[k] = g1w[k * 64 + j];
        wb[k] = g1w[(64 + k) * 64 + j];
    }
    float bj = h1b[j];

    const int NGROUPS = L_NODES / 4;   // 7500
    for (int grp = blockIdx.x; grp < NGROUPS; grp += gridDim.x) {
        int l = grp * 4 + g;

        const float4* xr = (const float4*)(X + l * NFEAT);
        float4 x0 = xr[0], x1 = xr[1], x2 = xr[2], x3 = xr[3];
        float acc = bj;
        acc = fmaf(x0.x, wh[ 0], acc); acc = fmaf(x0.y, wh[ 1], acc);
        acc = fmaf(x0.z, wh[ 2], acc); acc = fmaf(x0.w, wh[ 3], acc);
        acc = fmaf(x1.x, wh[ 4], acc); acc = fmaf(x1.y, wh[ 5], acc);
        acc = fmaf(x1.z, wh[ 6], acc); acc = fmaf(x1.w, wh[ 7], acc);
        acc = fmaf(x2.x, wh[ 8], acc); acc = fmaf(x2.y, wh[ 9], acc);
        acc = fmaf(x2.z, wh[10], acc); acc = fmaf(x2.w, wh[11], acc);
        acc = fmaf(x3.x, wh[12], acc); acc = fmaf(x3.y, wh[13], acc);
        acc = fmaf(x3.z, wh[14], acc); acc = fmaf(x3.w, wh[15], acc);
        s_hx[g][j] = fmaxf(acc, 0.0f);
        __syncthreads();

        float at = 0.0f, ab = 0.0f;
        const float4* vp = (const float4*)s_hx[g];
#pragma unroll
        for (int k4 = 0; k4 < 16; k4++) {
            float4 v = vp[k4];
            int r = 4 * k4;
            at = fmaf(v.x, wt[r + 0], at);  ab = fmaf(v.x, wb[r + 0], ab);
            at = fmaf(v.y, wt[r + 1], at);  ab = fmaf(v.y, wb[r + 1], ab);
            at = fmaf(v.z, wt[r + 2], at);  ab = fmaf(v.z, wb[r + 2], ab);
            at = fmaf(v.w, wt[r + 3], at);  ab = fmaf(v.w, wb[r + 3], ab);
        }
        g_hXWt[l * 64 + j] = at;
        g_hXWb[l * 64 + j] = ab;
        __syncthreads();
    }
}

// ---------------------------------------------------------------------------
// Main: 1 WARP per node, thread t owns columns t and t+32.
// Wb held as f32x2 k-pairs in 128 regs; broadcast vector read as LDS.64
// (v_2k, v_2k+1) -> each 8B crossbar delivery feeds 4 FFMA2 (8 FMAs).
// Crossbar bytes per node: 90KB (half of R4's 180KB). Warp-synchronous.
// ---------------------------------------------------------------------------
__global__ __launch_bounds__(256, 1) void ggcn_main_kernel(
    const int*   __restrict__ nbr,
    const float* __restrict__ g1w,
    const float* __restrict__ g1b,
    const float* __restrict__ fw,
    const float* __restrict__ fb,
    float*       __restrict__ out)
{
    __shared__ __align__(16) float s_v[8][6][64];   // per-warp staging, 12KB

    int warp = threadIdx.x >> 5;
    int t    = threadIdx.x & 31;
    int l    = blockIdx.x * 8 + warp;

    // Wb columns t, t+32 packed over k-pairs: wlo[k2]=(Wb[2k2][t],Wb[2k2+1][t])
    unsigned long long wlo[32], whi[32];
#pragma unroll
    for (int k2 = 0; k2 < 32; k2++) {
        wlo[k2] = pack2(g1w[(64 + 2 * k2) * 64 + t],
                        g1w[(64 + 2 * k2 + 1) * 64 + t]);
        whi[k2] = pack2(g1w[(64 + 2 * k2) * 64 + t + 32],
                        g1w[(64 + 2 * k2 + 1) * 64 + t + 32]);
    }
    float blo = g1b[t], bhi = g1b[t + 32];

    int4 nb = ((const int4*)nbr)[l];
    int ni[4] = {nb.x, nb.y, nb.z, nb.w};
    float Alo[4], Ahi[4], Blo[4], Bhi[4];
#pragma unroll
    for (int i = 0; i < 4; i++) {
        Alo[i] = g_hXWt[ni[i] * 64 + t];
        Ahi[i] = g_hXWt[ni[i] * 64 + t + 32];
        Blo[i] = g_hXWb[ni[i] * 64 + t];
        Bhi[i] = g_hXWb[ni[i] * 64 + t + 32];
    }
    float hxwtlo = g_hXWt[l * 64 + t];
    float hxwthi = g_hXWt[l * 64 + t + 32];

    // ---- pairs: stage pairf vectors ----
    const int PA[6] = {0, 0, 0, 1, 1, 2};
    const int PB[6] = {1, 2, 3, 2, 3, 3};
#pragma unroll
    for (int p = 0; p < 6; p++) {
        int i0 = PA[p], i1 = PB[p];
        s_v[warp][p][t] = 0.5f * (fmaxf(Alo[i0] + Blo[i1] + blo, 0.0f) +
                                  fmaxf(Alo[i1] + Blo[i0] + blo, 0.0f));
        s_v[warp][p][t + 32] = 0.5f * (fmaxf(Ahi[i0] + Bhi[i1] + bhi, 0.0f) +
                                       fmaxf(Ahi[i1] + Bhi[i0] + bhi, 0.0f));
    }
    __syncwarp();

    // ---- PWb = pairf @ Wb (6 matvecs, 2 at a time) ----
    float PWblo[6], PWbhi[6];
#pragma unroll
    for (int p = 0; p < 6; p += 2) {
        unsigned long long a0l = 0ull, a0h = 0ull, a1l = 0ull, a1h = 0ull;
        const unsigned long long* v0 = (const unsigned long long*)s_v[warp][p];
        const unsigned long long* v1 = (const unsigned long long*)s_v[warp][p + 1];
#pragma unroll
        for (int k2 = 0; k2 < 32; k2++) {
            unsigned long long v = v0[k2];
            unsigned long long u = v1[k2];
            ffma2(a0l, wlo[k2], v);  ffma2(a0h, whi[k2], v);
            ffma2(a1l, wlo[k2], u);  ffma2(a1h, whi[k2], u);
        }
        PWblo[p]     = hsum2(a0l);  PWbhi[p]     = hsum2(a0h);
        PWblo[p + 1] = hsum2(a1l);  PWbhi[p + 1] = hsum2(a1h);
    }
    __syncwarp();   // s_v about to be overwritten

    // ---- triples (indexed by missing element m) ----
    const int PIDX[4][4] = {{-1, 0, 1, 2},
                            { 0,-1, 3, 4},
                            { 1, 3,-1, 5},
                            { 2, 4, 5,-1}};
#pragma unroll
    for (int m = 0; m < 4; m++) {
        float aclo = 0.0f, achi = 0.0f;
#pragma unroll
        for (int i = 0; i < 4; i++) {
            if (i == m) continue;
            int a = -1, c = -1;
#pragma unroll
            for (int q = 0; q < 4; q++) {
                if (q != m && q != i) { if (a < 0) a = q; else c = q; }
            }
            int pi = PIDX[a][c];
            aclo += fmaxf(Alo[i] + PWblo[pi] + blo, 0.0f);
            achi += fmaxf(Ahi[i] + PWbhi[pi] + bhi, 0.0f);
        }
        s_v[warp][m][t]      = aclo * (1.0f / 3.0f);
        s_v[warp][m][t + 32] = achi * (1.0f / 3.0f);
    }
    __syncwarp();

    // ---- TWb = triplef @ Wb (4 matvecs, 2 at a time) ----
    float TWblo[4], TWbhi[4];
#pragma unroll
    for (int m = 0; m < 4; m += 2) {
        unsigned long long a0l = 0ull, a0h = 0ull, a1l = 0ull, a1h = 0ull;
        const unsigned long long* v0 = (const unsigned long long*)s_v[warp][m];
        const unsigned long long* v1 = (const unsigned long long*)s_v[warp][m + 1];
#pragma unroll
        for (int k2 = 0; k2 < 32; k2++) {
            unsigned long long v = v0[k2];
            unsigned long long u = v1[k2];
            ffma2(a0l, wlo[k2], v);  ffma2(a0h, whi[k2], v);
            ffma2(a1l, wlo[k2], u);  ffma2(a1h, whi[k2], u);
        }
        TWblo[m]     = hsum2(a0l);  TWbhi[m]     = hsum2(a0h);
        TWblo[m + 1] = hsum2(a1l);  TWbhi[m + 1] = hsum2(a1h);
    }
    __syncwarp();   // s_v reused for E

    // ---- quad + E ----
    float qlo = 0.0f, qhi = 0.0f;
#pragma unroll
    for (int i = 0; i < 4; i++) {
        qlo += fmaxf(Alo[i] + TWblo[i] + blo, 0.0f);
        qhi += fmaxf(Ahi[i] + TWbhi[i] + bhi, 0.0f);
    }
    s_v[warp][0][t]      = fmaxf(qlo * 0.25f, 0.0f);
    s_v[warp][0][t + 32] = fmaxf(qhi * 0.25f, 0.0f);
    __syncwarp();

    // ---- E2 = relu(hxwt + E@Wb + b) ----
    unsigned long long ael = 0ull, aeh = 0ull;
    {
        const unsigned long long* v0 = (const unsigned long long*)s_v[warp][0];
#pragma unroll
        for (int k2 = 0; k2 < 32; k2++) {
            unsigned long long v = v0[k2];
            ffma2(ael, wlo[k2], v);
            ffma2(aeh, whi[k2], v);
        }
    }
    float e2lo = fmaxf(hxwtlo + hsum2(ael) + blo, 0.0f);
    float e2hi = fmaxf(hxwthi + hsum2(aeh) + bhi, 0.0f);

    // ---- readout head: y = E2 @ final_w + final_b, warp shfl reduction ----
    float p0 = e2lo * fw[t * 2 + 0] + e2hi * fw[(t + 32) * 2 + 0];
    float p1 = e2lo * fw[t * 2 + 1] + e2hi * fw[(t + 32) * 2 + 1];
#pragma unroll
    for (int off = 16; off > 0; off >>= 1) {
        p0 += __shfl_xor_sync(0xffffffffu, p0, off);
        p1 += __shfl_xor_sync(0xffffffffu, p1, off);
    }
    if (t == 0) {
        out[l * 2 + 0] = p0 + fb[0];
        out[l * 2 + 1] = p1 + fb[1];
    }
}

// ---------------------------------------------------------------------------
// kernel_launch: graph-capturable, allocation-free.
// Inputs: X, neighbors, h1_w, h1_b, g1_w, g1_b, final_w, final_b
// ---------------------------------------------------------------------------
extern "C" void kernel_launch(void* const* d_in, const int* in_sizes, int n_in,
                              void* d_out, int out_size)
{
    const float* X    = (const float*)d_in[0];
    const int*   nbr  = (const int*)  d_in[1];
    const float* h1w  = (const float*)d_in[2];
    const float* h1b  = (const float*)d_in[3];
    const float* g1w  = (const float*)d_in[4];
    const float* g1b  = (const float*)d_in[5];
    const float* fw   = (const float*)d_in[6];
    const float* fb   = (const float*)d_in[7];
    float* out = (float*)d_out;

    (void)in_sizes; (void)n_in; (void)out_size;

    prep_kernel<<<592, 256>>>(X, h1w, h1b, g1w);
    ggcn_main_kernel<<<L_NODES / 8, 256>>>(nbr, g1w, g1b, fw, fb, out);
}